// round 5
// baseline (speedup 1.0000x reference)
#include <cuda_runtime.h>

#define B_ 4
#define L_ 2048
#define C_ 1024
#define H_ 16
#define D_ 64
#define MTOK (B_ * L_)   // 8192 rows of tokens

// Scratch (allocation-free rule: __device__ globals)
__device__ float g_S[(size_t)MTOK * 3 * C_];   // QKV  [8192, 3072]  (96 MB)
__device__ float g_Y[(size_t)MTOK * C_];       // attn out [8192, 1024] (32 MB)

// ---------------------------------------------------------------------------
// SGEMM: C[M,N] = A[M,K] @ B[K,N], all row-major. M%128==0, N%128==0, K%8==0.
// 128x128 block tile, BK=8, 256 threads, 8x8 per-thread micro-tile.
// ---------------------------------------------------------------------------
__global__ __launch_bounds__(256) void sgemm_kernel(
    const float* __restrict__ A, const float* __restrict__ B,
    float* __restrict__ C, int M, int N, int K)
{
    __shared__ float As[8][128];
    __shared__ float Bs[8][128];

    const int t  = threadIdx.x;
    const int bn = blockIdx.x * 128;
    const int bm = blockIdx.y * 128;
    const int ty = t >> 4;          // 0..15
    const int tx = t & 15;          // 0..15

    // A tile load mapping: 128 rows x 8 k, float4 along K
    const int row_a = t >> 1;          // 0..127
    const int kg    = (t & 1) * 4;     // 0 or 4
    // B tile load mapping: 8 k-rows x 128 n, float4 along N
    const int kr = t >> 5;             // 0..7
    const int n4 = (t & 31) * 4;       // 0..124

    const float* Aptr = A + (bm + row_a) * K + kg;
    const float* Bptr = B + kr * N + bn + n4;

    float acc[8][8];
#pragma unroll
    for (int i = 0; i < 8; i++)
#pragma unroll
        for (int j = 0; j < 8; j++) acc[i][j] = 0.f;

    for (int kt = 0; kt < K; kt += 8) {
        float4 av = *(const float4*)(Aptr + kt);
        As[kg + 0][row_a] = av.x;
        As[kg + 1][row_a] = av.y;
        As[kg + 2][row_a] = av.z;
        As[kg + 3][row_a] = av.w;
        float4 bv = *(const float4*)(Bptr + kt * N);
        *(float4*)&Bs[kr][n4] = bv;
        __syncthreads();

#pragma unroll
        for (int k = 0; k < 8; k++) {
            float a[8], b[8];
            *(float4*)&a[0] = *(const float4*)&As[k][ty * 8];
            *(float4*)&a[4] = *(const float4*)&As[k][ty * 8 + 4];
            *(float4*)&b[0] = *(const float4*)&Bs[k][tx * 8];
            *(float4*)&b[4] = *(const float4*)&Bs[k][tx * 8 + 4];
#pragma unroll
            for (int i = 0; i < 8; i++)
#pragma unroll
                for (int j = 0; j < 8; j++)
                    acc[i][j] += a[i] * b[j];
        }
        __syncthreads();
    }

    float* Cp = C + (bm + ty * 8) * N + bn + tx * 8;
#pragma unroll
    for (int i = 0; i < 8; i++) {
        *(float4*)(Cp + i * N)     = make_float4(acc[i][0], acc[i][1], acc[i][2], acc[i][3]);
        *(float4*)(Cp + i * N + 4) = make_float4(acc[i][4], acc[i][5], acc[i][6], acc[i][7]);
    }
}

// ---------------------------------------------------------------------------
// Flash attention (fp32). One CTA per (q-tile of 64, head, batch).
// S layout: [MTOK, 3C]; Q cols [h*64, h*64+64), K cols [C + h*64 ...),
// V cols [2C + h*64 ...).
// smem: Qs[64][64], Kts[64][68] (transposed: [d][key]), Vs[64][64], Ps[64][64]
// Thread (ty,tx): owns query rows ty*4+{0..3}; cols tx*4+{0..3} (keys in QK^T,
// head-dims in PV / output).
// ---------------------------------------------------------------------------
#define KTS_LD 68
#define ATTN_SMEM ((64 * 64 + 64 * KTS_LD + 64 * 64 + 64 * 64) * 4)

__global__ __launch_bounds__(256) void attn_kernel(
    const float* __restrict__ S, float* __restrict__ Y)
{
    extern __shared__ float sm[];
    float* Qs  = sm;                       // [64][64]
    float* Kts = Qs + 64 * 64;             // [64][KTS_LD]  ([d][key])
    float* Vs  = Kts + 64 * KTS_LD;        // [64][64]      ([key][d])
    float* Ps  = Vs + 64 * 64;             // [64][64]

    const int it = blockIdx.x;     // q-tile index (0..31)
    const int h  = blockIdx.y;
    const int b  = blockIdx.z;
    const int t  = threadIdx.x;
    const int ty = t >> 4, tx = t & 15;

    const int q0 = it * 64;
    const float* Sb   = S + (size_t)b * L_ * 3 * C_;
    const int   qcol  = h * D_;
    const int   kcol  = C_ + h * D_;
    const int   vcol  = 2 * C_ + h * D_;

    // Load Q tile (coalesced float4)
#pragma unroll
    for (int i = 0; i < 4; i++) {
        int idx = t + 256 * i;
        int row = idx >> 4;
        int c4  = (idx & 15) * 4;
        *(float4*)&Qs[row * 64 + c4] =
            *(const float4*)&Sb[(q0 + row) * 3 * C_ + qcol + c4];
    }

    float m[4], l[4], O[4][4];
#pragma unroll
    for (int i = 0; i < 4; i++) {
        m[i] = -1e30f; l[i] = 0.f;
#pragma unroll
        for (int j = 0; j < 4; j++) O[i][j] = 0.f;
    }

    const float scale = 0.125f;   // 1/sqrt(64)

    for (int jb = 0; jb <= it; jb++) {
        const int k0 = jb * 64;
        __syncthreads();   // previous iter consumers done (also covers Q load)

        // Load K (transposed into Kts[d][key]) and V
#pragma unroll
        for (int i = 0; i < 4; i++) {
            int idx = t + 256 * i;
            int row = idx >> 4;          // key within tile
            int c4  = (idx & 15) * 4;    // d
            float4 kv = *(const float4*)&Sb[(k0 + row) * 3 * C_ + kcol + c4];
            Kts[(c4 + 0) * KTS_LD + row] = kv.x;
            Kts[(c4 + 1) * KTS_LD + row] = kv.y;
            Kts[(c4 + 2) * KTS_LD + row] = kv.z;
            Kts[(c4 + 3) * KTS_LD + row] = kv.w;
            *(float4*)&Vs[row * 64 + c4] =
                *(const float4*)&Sb[(k0 + row) * 3 * C_ + vcol + c4];
        }
        __syncthreads();

        // S = Q K^T for this tile pair
        float s[4][4];
#pragma unroll
        for (int i = 0; i < 4; i++)
#pragma unroll
            for (int j = 0; j < 4; j++) s[i][j] = 0.f;

#pragma unroll 8
        for (int d = 0; d < 64; d++) {
            float4 kvv = *(const float4*)&Kts[d * KTS_LD + tx * 4];
            float q0v = Qs[(ty * 4 + 0) * 64 + d];
            float q1v = Qs[(ty * 4 + 1) * 64 + d];
            float q2v = Qs[(ty * 4 + 2) * 64 + d];
            float q3v = Qs[(ty * 4 + 3) * 64 + d];
            s[0][0] += q0v * kvv.x; s[0][1] += q0v * kvv.y; s[0][2] += q0v * kvv.z; s[0][3] += q0v * kvv.w;
            s[1][0] += q1v * kvv.x; s[1][1] += q1v * kvv.y; s[1][2] += q1v * kvv.z; s[1][3] += q1v * kvv.w;
            s[2][0] += q2v * kvv.x; s[2][1] += q2v * kvv.y; s[2][2] += q2v * kvv.z; s[2][3] += q2v * kvv.w;
            s[3][0] += q3v * kvv.x; s[3][1] += q3v * kvv.y; s[3][2] += q3v * kvv.z; s[3][3] += q3v * kvv.w;
        }

        // scale + causal mask (only the diagonal tile actually masks)
        const bool diag = (jb == it);
#pragma unroll
        for (int i = 0; i < 4; i++) {
            int qi = q0 + ty * 4 + i;
#pragma unroll
            for (int j = 0; j < 4; j++) {
                int ki = k0 + tx * 4 + j;
                s[i][j] = (diag && ki > qi) ? -1e30f : s[i][j] * scale;
            }
        }

        // online softmax update
#pragma unroll
        for (int i = 0; i < 4; i++) {
            float rmax = fmaxf(fmaxf(s[i][0], s[i][1]), fmaxf(s[i][2], s[i][3]));
            rmax = fmaxf(rmax, __shfl_xor_sync(0xffffffffu, rmax, 1));
            rmax = fmaxf(rmax, __shfl_xor_sync(0xffffffffu, rmax, 2));
            rmax = fmaxf(rmax, __shfl_xor_sync(0xffffffffu, rmax, 4));
            rmax = fmaxf(rmax, __shfl_xor_sync(0xffffffffu, rmax, 8));
            float nm = fmaxf(m[i], rmax);
            float alpha = __expf(m[i] - nm);
            m[i] = nm;
            float p0 = __expf(s[i][0] - nm);
            float p1 = __expf(s[i][1] - nm);
            float p2 = __expf(s[i][2] - nm);
            float p3 = __expf(s[i][3] - nm);
            float rs = p0 + p1 + p2 + p3;
            rs += __shfl_xor_sync(0xffffffffu, rs, 1);
            rs += __shfl_xor_sync(0xffffffffu, rs, 2);
            rs += __shfl_xor_sync(0xffffffffu, rs, 4);
            rs += __shfl_xor_sync(0xffffffffu, rs, 8);
            l[i] = l[i] * alpha + rs;
            O[i][0] *= alpha; O[i][1] *= alpha; O[i][2] *= alpha; O[i][3] *= alpha;
            *(float4*)&Ps[(ty * 4 + i) * 64 + tx * 4] = make_float4(p0, p1, p2, p3);
        }
        __syncthreads();

        // O += P @ V  (thread owns d-cols tx*4..tx*4+3)
#pragma unroll 8
        for (int c = 0; c < 64; c++) {
            float4 vv = *(const float4*)&Vs[c * 64 + tx * 4];
            float p0 = Ps[(ty * 4 + 0) * 64 + c];
            float p1 = Ps[(ty * 4 + 1) * 64 + c];
            float p2 = Ps[(ty * 4 + 2) * 64 + c];
            float p3 = Ps[(ty * 4 + 3) * 64 + c];
            O[0][0] += p0 * vv.x; O[0][1] += p0 * vv.y; O[0][2] += p0 * vv.z; O[0][3] += p0 * vv.w;
            O[1][0] += p1 * vv.x; O[1][1] += p1 * vv.y; O[1][2] += p1 * vv.z; O[1][3] += p1 * vv.w;
            O[2][0] += p2 * vv.x; O[2][1] += p2 * vv.y; O[2][2] += p2 * vv.z; O[2][3] += p2 * vv.w;
            O[3][0] += p3 * vv.x; O[3][1] += p3 * vv.y; O[3][2] += p3 * vv.z; O[3][3] += p3 * vv.w;
        }
    }

    // normalize + write Y[b, q, h*64 + d]
#pragma unroll
    for (int i = 0; i < 4; i++) {
        float inv = 1.0f / l[i];
        float4 o = make_float4(O[i][0] * inv, O[i][1] * inv, O[i][2] * inv, O[i][3] * inv);
        *(float4*)&Y[(size_t)(b * L_ + q0 + ty * 4 + i) * C_ + h * D_ + tx * 4] = o;
    }
}

// ---------------------------------------------------------------------------

extern "C" void kernel_launch(void* const* d_in, const int* in_sizes, int n_in,
                              void* d_out, int out_size)
{
    const float* x      = (const float*)d_in[0];   // [4,2048,1024]
    const float* w_attn = (const float*)d_in[1];   // [1024,3072]
    const float* w_proj = (const float*)d_in[2];   // [1024,1024]
    float* out = (float*)d_out;                    // [4,2048,1024]

    float *sbuf = nullptr, *ybuf = nullptr;
    cudaGetSymbolAddress((void**)&sbuf, g_S);
    cudaGetSymbolAddress((void**)&ybuf, g_Y);

    cudaFuncSetAttribute(attn_kernel,
                         cudaFuncAttributeMaxDynamicSharedMemorySize, ATTN_SMEM);

    // 1) QKV projection: [8192,1024] @ [1024,3072]
    sgemm_kernel<<<dim3(3 * C_ / 128, MTOK / 128), 256>>>(
        x, w_attn, sbuf, MTOK, 3 * C_, C_);

    // 2) causal flash attention
    attn_kernel<<<dim3(L_ / 64, H_, B_), 256, ATTN_SMEM>>>(sbuf, ybuf);

    // 3) output projection: [8192,1024] @ [1024,1024]
    sgemm_kernel<<<dim3(C_ / 128, MTOK / 128), 256>>>(
        ybuf, w_proj, out, MTOK, C_, C_);
}

// round 9
// speedup vs baseline: 1.5604x; 1.5604x over previous
#include <cuda_runtime.h>
#include <cuda_bf16.h>
#include <cstdint>

#define B_ 4
#define L_ 2048
#define C_ 1024
#define H_ 16
#define D_ 64
#define MTOK (B_ * L_)   // 8192 token rows

// ---------------------------------------------------------------------------
// Scratch (allocation-free rule: __device__ globals)
// ---------------------------------------------------------------------------
__device__ float g_S[(size_t)MTOK * 3 * C_];          // QKV  [8192, 3072] fp32
__device__ float g_Y[(size_t)MTOK * C_];              // attn out [8192, 1024] fp32
__device__ __nv_bfloat16 g_Ahi[(size_t)MTOK * C_];    // activation hi  [M,K]
__device__ __nv_bfloat16 g_Alo[(size_t)MTOK * C_];    // activation lo  [M,K]
__device__ __nv_bfloat16 g_Bhi[(size_t)3 * C_ * C_];  // weight^T hi    [N,K]
__device__ __nv_bfloat16 g_Blo[(size_t)3 * C_ * C_];  // weight^T lo    [N,K]

// ---------------------------------------------------------------------------
// helpers
// ---------------------------------------------------------------------------
__device__ __forceinline__ uint32_t smem_u32(const void* p) {
    return (uint32_t)__cvta_generic_to_shared(p);
}
__device__ __forceinline__ void cp16(void* s, const void* g) {
    uint32_t sa = smem_u32(s);
    asm volatile("cp.async.cg.shared.global [%0], [%1], 16;" :: "r"(sa), "l"(g) : "memory");
}
__device__ __forceinline__ void ldx4(uint32_t* r, uint32_t addr) {
    asm volatile("ldmatrix.sync.aligned.m8n8.x4.shared.b16 {%0,%1,%2,%3}, [%4];"
                 : "=r"(r[0]), "=r"(r[1]), "=r"(r[2]), "=r"(r[3]) : "r"(addr));
}
__device__ __forceinline__ void mma_bf16(float* d, const uint32_t* a, const uint32_t* b) {
    asm volatile(
        "mma.sync.aligned.m16n8k16.row.col.f32.bf16.bf16.f32 "
        "{%0,%1,%2,%3}, {%4,%5,%6,%7}, {%8,%9}, {%0,%1,%2,%3};"
        : "+f"(d[0]), "+f"(d[1]), "+f"(d[2]), "+f"(d[3])
        : "r"(a[0]), "r"(a[1]), "r"(a[2]), "r"(a[3]), "r"(b[0]), "r"(b[1]));
}

// ---------------------------------------------------------------------------
// fp32 -> bf16 hi/lo split (same layout)
// ---------------------------------------------------------------------------
__global__ __launch_bounds__(256) void cvt_hilo(
    const float* __restrict__ in, __nv_bfloat16* __restrict__ hi,
    __nv_bfloat16* __restrict__ lo, int n)
{
    int i = (blockIdx.x * 256 + threadIdx.x) * 4;
    if (i >= n) return;
    float4 v = *(const float4*)(in + i);
    float f[4] = {v.x, v.y, v.z, v.w};
    __align__(8) __nv_bfloat16 hb[4];
    __align__(8) __nv_bfloat16 lb[4];
#pragma unroll
    for (int j = 0; j < 4; j++) {
        hb[j] = __float2bfloat16(f[j]);
        lb[j] = __float2bfloat16(f[j] - __bfloat162float(hb[j]));
    }
    *(uint2*)(hi + i) = *(uint2*)hb;
    *(uint2*)(lo + i) = *(uint2*)lb;
}

// ---------------------------------------------------------------------------
// W [K,N] fp32 row-major -> W^T hi/lo bf16 [N,K]
// ---------------------------------------------------------------------------
__global__ __launch_bounds__(256) void cvt_w_t(
    const float* __restrict__ W, __nv_bfloat16* __restrict__ Thi,
    __nv_bfloat16* __restrict__ Tlo, int K, int N)
{
    __shared__ float tile[32][33];
    const int n0 = blockIdx.x * 32, k0 = blockIdx.y * 32;
    const int tx = threadIdx.x & 31, ty = threadIdx.x >> 5;   // 32 x 8
#pragma unroll
    for (int r = 0; r < 4; r++)
        tile[ty + 8 * r][tx] = W[(size_t)(k0 + ty + 8 * r) * N + n0 + tx];
    __syncthreads();
#pragma unroll
    for (int r = 0; r < 4; r++) {
        int n = n0 + ty + 8 * r;
        float v = tile[tx][ty + 8 * r];
        __nv_bfloat16 h = __float2bfloat16(v);
        __nv_bfloat16 l = __float2bfloat16(v - __bfloat162float(h));
        Thi[(size_t)n * K + k0 + tx] = h;
        Tlo[(size_t)n * K + k0 + tx] = l;
    }
}

// ---------------------------------------------------------------------------
// mma.sync bf16x3 GEMM: C[M,N] = A[M,K] @ B^T  (A [M,K], B [N,K], hi/lo bf16)
// CTA: 128x128 tile, BK=32, 256 threads (8 warps, 2Mx4N, warp tile 64x32),
// cp.async double-buffered.
// ---------------------------------------------------------------------------
#define BK_G   32
#define LDT    40                       // 32 + 8 pad (bf16 elems) -> 80B rows
#define MAT_B  (128 * LDT * 2)          // 10240 B per matrix (128 rows)
#define BUF_B  (4 * MAT_B)              // Ahi Alo Bhi Blo = 40960 B
#define SMEM_GEMM (2 * BUF_B)           // 81920 B

__global__ __launch_bounds__(256, 1)
void gemm_mma_bf16x3(const __nv_bfloat16* __restrict__ Ahi,
                     const __nv_bfloat16* __restrict__ Alo,
                     const __nv_bfloat16* __restrict__ Bhi,
                     const __nv_bfloat16* __restrict__ Blo,
                     float* __restrict__ Cmat, int N, int K)
{
    extern __shared__ __align__(128) char smem[];
    const int t    = threadIdx.x;
    const int lane = t & 31;
    const int wid  = t >> 5;
    const int bn   = blockIdx.x * 128;
    const int bm   = blockIdx.y * 128;
    const int wm   = (wid & 1) * 64;    // warp M offset (2 warps in M)
    const int wn   = (wid >> 1) * 32;   // warp N offset (4 warps in N)

    float acc[4][4][4];
#pragma unroll
    for (int i = 0; i < 4; i++)
#pragma unroll
        for (int j = 0; j < 4; j++)
#pragma unroll
            for (int r = 0; r < 4; r++) acc[i][j][r] = 0.f;

    const int nk = K / BK_G;

    // ---- tile loader: 2 iters x 4 cp.async per thread --------------------
    auto load_tile = [&](int c, int buf) {
        char* bp = smem + buf * BUF_B;
        const int kc = c * BK_G;
#pragma unroll
        for (int i = 0; i < 2; i++) {
            int idx = t + 256 * i;
            int row = idx >> 2;            // 0..127
            int c16 = idx & 3;             // 16B chunk within 64B row
            uint32_t so = (uint32_t)(row * LDT + c16 * 8) * 2;
            size_t ga = (size_t)(bm + row) * K + kc + c16 * 8;
            size_t gb = (size_t)(bn + row) * K + kc + c16 * 8;
            cp16(bp + so,             Ahi + ga);
            cp16(bp + MAT_B + so,     Alo + ga);
            cp16(bp + 2 * MAT_B + so, Bhi + gb);
            cp16(bp + 3 * MAT_B + so, Blo + gb);
        }
    };

    load_tile(0, 0);
    asm volatile("cp.async.commit_group;" ::: "memory");

    for (int c = 0; c < nk; c++) {
        if (c + 1 < nk) {
            load_tile(c + 1, (c + 1) & 1);
            asm volatile("cp.async.commit_group;" ::: "memory");
            asm volatile("cp.async.wait_group 1;" ::: "memory");
        } else {
            asm volatile("cp.async.wait_group 0;" ::: "memory");
        }
        __syncthreads();

        const char* bp = smem + (c & 1) * BUF_B;
        const __nv_bfloat16* sAhi = (const __nv_bfloat16*)(bp);
        const __nv_bfloat16* sAlo = (const __nv_bfloat16*)(bp + MAT_B);
        const __nv_bfloat16* sBhi = (const __nv_bfloat16*)(bp + 2 * MAT_B);
        const __nv_bfloat16* sBlo = (const __nv_bfloat16*)(bp + 3 * MAT_B);

#pragma unroll
        for (int ks = 0; ks < BK_G; ks += 16) {
            uint32_t ah[4][4], al[4][4], bh[2][4], bl[2][4];
            // A frags: 16x16 tiles at m = wm + mf*16
            const int arow = lane & 15;
            const int acol = ks + (lane >> 4) * 8;
#pragma unroll
            for (int mf = 0; mf < 4; mf++) {
                uint32_t off = (uint32_t)((wm + mf * 16 + arow) * LDT + acol);
                ldx4(ah[mf], smem_u32(sAhi + off));
                ldx4(al[mf], smem_u32(sAlo + off));
            }
            // B frags: 16n x 16k tiles at n = wn + nf2*16
            const int g    = lane >> 3;                    // 0..3
            const int brow = ((g >> 1) << 3) + (lane & 7); // n within 16
            const int bcol = ks + (g & 1) * 8;
#pragma unroll
            for (int nf2 = 0; nf2 < 2; nf2++) {
                uint32_t off = (uint32_t)((wn + nf2 * 16 + brow) * LDT + bcol);
                ldx4(bh[nf2], smem_u32(sBhi + off));
                ldx4(bl[nf2], smem_u32(sBlo + off));
            }
#pragma unroll
            for (int mf = 0; mf < 4; mf++)
#pragma unroll
                for (int nf2 = 0; nf2 < 2; nf2++)
#pragma unroll
                    for (int j = 0; j < 2; j++) {
                        float* d = acc[mf][nf2 * 2 + j];
                        mma_bf16(d, ah[mf], &bh[nf2][j * 2]);
                        mma_bf16(d, ah[mf], &bl[nf2][j * 2]);
                        mma_bf16(d, al[mf], &bh[nf2][j * 2]);
                    }
        }
        __syncthreads();
    }

    // epilogue: acc[mf][nf]: rows lane/4 (+8), cols (lane%4)*2
#pragma unroll
    for (int mf = 0; mf < 4; mf++)
#pragma unroll
        for (int nf = 0; nf < 4; nf++) {
            int row = bm + wm + mf * 16 + (lane >> 2);
            int col = bn + wn + nf * 8 + (lane & 3) * 2;
            *(float2*)&Cmat[(size_t)row * N + col] =
                make_float2(acc[mf][nf][0], acc[mf][nf][1]);
            *(float2*)&Cmat[(size_t)(row + 8) * N + col] =
                make_float2(acc[mf][nf][2], acc[mf][nf][3]);
        }
}

// ---------------------------------------------------------------------------
// Flash attention (fp32) — unchanged (passing). One CTA per (64 q, h, b).
// ---------------------------------------------------------------------------
#define KTS_LD 68
#define ATTN_SMEM ((64 * 64 + 64 * KTS_LD + 64 * 64 + 64 * 64) * 4)

__global__ __launch_bounds__(256) void attn_kernel(
    const float* __restrict__ S, float* __restrict__ Y)
{
    extern __shared__ float sm[];
    float* Qs  = sm;
    float* Kts = Qs + 64 * 64;
    float* Vs  = Kts + 64 * KTS_LD;
    float* Ps  = Vs + 64 * 64;

    const int it = blockIdx.x;
    const int h  = blockIdx.y;
    const int b  = blockIdx.z;
    const int t  = threadIdx.x;
    const int ty = t >> 4, tx = t & 15;

    const int q0 = it * 64;
    const float* Sb  = S + (size_t)b * L_ * 3 * C_;
    const int   qcol = h * D_;
    const int   kcol = C_ + h * D_;
    const int   vcol = 2 * C_ + h * D_;

#pragma unroll
    for (int i = 0; i < 4; i++) {
        int idx = t + 256 * i;
        int row = idx >> 4;
        int c4  = (idx & 15) * 4;
        *(float4*)&Qs[row * 64 + c4] =
            *(const float4*)&Sb[(q0 + row) * 3 * C_ + qcol + c4];
    }

    float m[4], l[4], O[4][4];
#pragma unroll
    for (int i = 0; i < 4; i++) {
        m[i] = -1e30f; l[i] = 0.f;
#pragma unroll
        for (int j = 0; j < 4; j++) O[i][j] = 0.f;
    }
    const float scale = 0.125f;

    for (int jb = 0; jb <= it; jb++) {
        const int k0 = jb * 64;
        __syncthreads();
#pragma unroll
        for (int i = 0; i < 4; i++) {
            int idx = t + 256 * i;
            int row = idx >> 4;
            int c4  = (idx & 15) * 4;
            float4 kv = *(const float4*)&Sb[(k0 + row) * 3 * C_ + kcol + c4];
            Kts[(c4 + 0) * KTS_LD + row] = kv.x;
            Kts[(c4 + 1) * KTS_LD + row] = kv.y;
            Kts[(c4 + 2) * KTS_LD + row] = kv.z;
            Kts[(c4 + 3) * KTS_LD + row] = kv.w;
            *(float4*)&Vs[row * 64 + c4] =
                *(const float4*)&Sb[(k0 + row) * 3 * C_ + vcol + c4];
        }
        __syncthreads();

        float s[4][4];
#pragma unroll
        for (int i = 0; i < 4; i++)
#pragma unroll
            for (int j = 0; j < 4; j++) s[i][j] = 0.f;

#pragma unroll 8
        for (int d = 0; d < 64; d++) {
            float4 kvv = *(const float4*)&Kts[d * KTS_LD + tx * 4];
            float q0v = Qs[(ty * 4 + 0) * 64 + d];
            float q1v = Qs[(ty * 4 + 1) * 64 + d];
            float q2v = Qs[(ty * 4 + 2) * 64 + d];
            float q3v = Qs[(ty * 4 + 3) * 64 + d];
            s[0][0] += q0v * kvv.x; s[0][1] += q0v * kvv.y; s[0][2] += q0v * kvv.z; s[0][3] += q0v * kvv.w;
            s[1][0] += q1v * kvv.x; s[1][1] += q1v * kvv.y; s[1][2] += q1v * kvv.z; s[1][3] += q1v * kvv.w;
            s[2][0] += q2v * kvv.x; s[2][1] += q2v * kvv.y; s[2][2] += q2v * kvv.z; s[2][3] += q2v * kvv.w;
            s[3][0] += q3v * kvv.x; s[3][1] += q3v * kvv.y; s[3][2] += q3v * kvv.z; s[3][3] += q3v * kvv.w;
        }

        const bool diag = (jb == it);
#pragma unroll
        for (int i = 0; i < 4; i++) {
            int qi = q0 + ty * 4 + i;
#pragma unroll
            for (int j = 0; j < 4; j++) {
                int ki = k0 + tx * 4 + j;
                s[i][j] = (diag && ki > qi) ? -1e30f : s[i][j] * scale;
            }
        }

#pragma unroll
        for (int i = 0; i < 4; i++) {
            float rmax = fmaxf(fmaxf(s[i][0], s[i][1]), fmaxf(s[i][2], s[i][3]));
            rmax = fmaxf(rmax, __shfl_xor_sync(0xffffffffu, rmax, 1));
            rmax = fmaxf(rmax, __shfl_xor_sync(0xffffffffu, rmax, 2));
            rmax = fmaxf(rmax, __shfl_xor_sync(0xffffffffu, rmax, 4));
            rmax = fmaxf(rmax, __shfl_xor_sync(0xffffffffu, rmax, 8));
            float nm = fmaxf(m[i], rmax);
            float alpha = __expf(m[i] - nm);
            m[i] = nm;
            float p0 = __expf(s[i][0] - nm);
            float p1 = __expf(s[i][1] - nm);
            float p2 = __expf(s[i][2] - nm);
            float p3 = __expf(s[i][3] - nm);
            float rs = p0 + p1 + p2 + p3;
            rs += __shfl_xor_sync(0xffffffffu, rs, 1);
            rs += __shfl_xor_sync(0xffffffffu, rs, 2);
            rs += __shfl_xor_sync(0xffffffffu, rs, 4);
            rs += __shfl_xor_sync(0xffffffffu, rs, 8);
            l[i] = l[i] * alpha + rs;
            O[i][0] *= alpha; O[i][1] *= alpha; O[i][2] *= alpha; O[i][3] *= alpha;
            *(float4*)&Ps[(ty * 4 + i) * 64 + tx * 4] = make_float4(p0, p1, p2, p3);
        }
        __syncthreads();

#pragma unroll 8
        for (int cc = 0; cc < 64; cc++) {
            float4 vv = *(const float4*)&Vs[cc * 64 + tx * 4];
            float p0 = Ps[(ty * 4 + 0) * 64 + cc];
            float p1 = Ps[(ty * 4 + 1) * 64 + cc];
            float p2 = Ps[(ty * 4 + 2) * 64 + cc];
            float p3 = Ps[(ty * 4 + 3) * 64 + cc];
            O[0][0] += p0 * vv.x; O[0][1] += p0 * vv.y; O[0][2] += p0 * vv.z; O[0][3] += p0 * vv.w;
            O[1][0] += p1 * vv.x; O[1][1] += p1 * vv.y; O[1][2] += p1 * vv.z; O[1][3] += p1 * vv.w;
            O[2][0] += p2 * vv.x; O[2][1] += p2 * vv.y; O[2][2] += p2 * vv.z; O[2][3] += p2 * vv.w;
            O[3][0] += p3 * vv.x; O[3][1] += p3 * vv.y; O[3][2] += p3 * vv.z; O[3][3] += p3 * vv.w;
        }
    }

#pragma unroll
    for (int i = 0; i < 4; i++) {
        float inv = 1.0f / l[i];
        float4 o = make_float4(O[i][0] * inv, O[i][1] * inv, O[i][2] * inv, O[i][3] * inv);
        *(float4*)&Y[(size_t)(b * L_ + q0 + ty * 4 + i) * C_ + h * D_ + tx * 4] = o;
    }
}

// ---------------------------------------------------------------------------

extern "C" void kernel_launch(void* const* d_in, const int* in_sizes, int n_in,
                              void* d_out, int out_size)
{
    const float* x      = (const float*)d_in[0];   // [4,2048,1024]
    const float* w_attn = (const float*)d_in[1];   // [1024,3072]
    const float* w_proj = (const float*)d_in[2];   // [1024,1024]
    float* out = (float*)d_out;                    // [4,2048,1024]

    float *sbuf = nullptr, *ybuf = nullptr;
    __nv_bfloat16 *ahi, *alo, *bhi, *blo;
    cudaGetSymbolAddress((void**)&sbuf, g_S);
    cudaGetSymbolAddress((void**)&ybuf, g_Y);
    cudaGetSymbolAddress((void**)&ahi, g_Ahi);
    cudaGetSymbolAddress((void**)&alo, g_Alo);
    cudaGetSymbolAddress((void**)&bhi, g_Bhi);
    cudaGetSymbolAddress((void**)&blo, g_Blo);

    cudaFuncSetAttribute(attn_kernel,
                         cudaFuncAttributeMaxDynamicSharedMemorySize, ATTN_SMEM);
    cudaFuncSetAttribute(gemm_mma_bf16x3,
                         cudaFuncAttributeMaxDynamicSharedMemorySize, SMEM_GEMM);

    const int nA = MTOK * C_;

    // 1) split x -> bf16 hi/lo ; transpose+split w_attn -> [3C, C]
    cvt_hilo<<<nA / 4 / 256, 256>>>(x, ahi, alo, nA);
    cvt_w_t<<<dim3(3 * C_ / 32, C_ / 32), 256>>>(w_attn, bhi, blo, C_, 3 * C_);

    // 2) QKV GEMM: [8192,1024] x [1024,3072]^T-layout -> g_S
    gemm_mma_bf16x3<<<dim3(3 * C_ / 128, MTOK / 128), 256, SMEM_GEMM>>>(
        ahi, alo, bhi, blo, sbuf, 3 * C_, C_);

    // 3) causal flash attention -> g_Y
    attn_kernel<<<dim3(L_ / 64, H_, B_), 256, ATTN_SMEM>>>(sbuf, ybuf);

    // 4) split Y ; transpose+split w_proj -> [C, C]
    cvt_hilo<<<nA / 4 / 256, 256>>>(ybuf, ahi, alo, nA);
    cvt_w_t<<<dim3(C_ / 32, C_ / 32), 256>>>(w_proj, bhi, blo, C_, C_);

    // 5) proj GEMM: [8192,1024] x [1024,1024]^T-layout -> out
    gemm_mma_bf16x3<<<dim3(C_ / 128, MTOK / 128), 256, SMEM_GEMM>>>(
        ahi, alo, bhi, blo, out, C_, C_);
}

// round 10
// speedup vs baseline: 2.7186x; 1.7422x over previous
#include <cuda_runtime.h>
#include <cuda_bf16.h>
#include <cstdint>

#define B_ 4
#define L_ 2048
#define C_ 1024
#define H_ 16
#define D_ 64
#define MTOK (B_ * L_)   // 8192 token rows

// ---------------------------------------------------------------------------
// Scratch (allocation-free rule: __device__ globals)
// ---------------------------------------------------------------------------
__device__ __nv_bfloat16 g_Ahi[(size_t)MTOK * C_];     // activation hi  [M,K]
__device__ __nv_bfloat16 g_Alo[(size_t)MTOK * C_];     // activation lo  [M,K]
__device__ __nv_bfloat16 g_Bhi[(size_t)3 * C_ * C_];   // weight^T hi    [N,K]
__device__ __nv_bfloat16 g_Blo[(size_t)3 * C_ * C_];   // weight^T lo    [N,K]
__device__ __nv_bfloat16 g_Shi[(size_t)MTOK * 3 * C_]; // QKV hi [8192,3072]
__device__ __nv_bfloat16 g_Slo[(size_t)MTOK * 3 * C_]; // QKV lo

// ---------------------------------------------------------------------------
// helpers
// ---------------------------------------------------------------------------
__device__ __forceinline__ uint32_t smem_u32(const void* p) {
    return (uint32_t)__cvta_generic_to_shared(p);
}
__device__ __forceinline__ void cp16(void* s, const void* g) {
    uint32_t sa = smem_u32(s);
    asm volatile("cp.async.cg.shared.global [%0], [%1], 16;" :: "r"(sa), "l"(g) : "memory");
}
__device__ __forceinline__ void ldx4(uint32_t* r, uint32_t addr) {
    asm volatile("ldmatrix.sync.aligned.m8n8.x4.shared.b16 {%0,%1,%2,%3}, [%4];"
                 : "=r"(r[0]), "=r"(r[1]), "=r"(r[2]), "=r"(r[3]) : "r"(addr));
}
__device__ __forceinline__ void ldx4t(uint32_t* r, uint32_t addr) {
    asm volatile("ldmatrix.sync.aligned.m8n8.x4.trans.shared.b16 {%0,%1,%2,%3}, [%4];"
                 : "=r"(r[0]), "=r"(r[1]), "=r"(r[2]), "=r"(r[3]) : "r"(addr));
}
__device__ __forceinline__ void mma_bf16(float* d, const uint32_t* a, const uint32_t* b) {
    asm volatile(
        "mma.sync.aligned.m16n8k16.row.col.f32.bf16.bf16.f32 "
        "{%0,%1,%2,%3}, {%4,%5,%6,%7}, {%8,%9}, {%0,%1,%2,%3};"
        : "+f"(d[0]), "+f"(d[1]), "+f"(d[2]), "+f"(d[3])
        : "r"(a[0]), "r"(a[1]), "r"(a[2]), "r"(a[3]), "r"(b[0]), "r"(b[1]));
}
// pack two floats into bf16x2 hi + bf16x2 lo (residual)
__device__ __forceinline__ void pack_hilo(float a, float b, uint32_t& h, uint32_t& l) {
    __nv_bfloat162 hv = __floats2bfloat162_rn(a, b);
    float2 hf = __bfloat1622float2(hv);
    __nv_bfloat162 lv = __floats2bfloat162_rn(a - hf.x, b - hf.y);
    h = *(uint32_t*)&hv;
    l = *(uint32_t*)&lv;
}

// ---------------------------------------------------------------------------
// fp32 -> bf16 hi/lo split (same layout)
// ---------------------------------------------------------------------------
__global__ __launch_bounds__(256) void cvt_hilo(
    const float* __restrict__ in, __nv_bfloat16* __restrict__ hi,
    __nv_bfloat16* __restrict__ lo, int n)
{
    int i = (blockIdx.x * 256 + threadIdx.x) * 4;
    if (i >= n) return;
    float4 v = *(const float4*)(in + i);
    float f[4] = {v.x, v.y, v.z, v.w};
    __align__(8) __nv_bfloat16 hb[4];
    __align__(8) __nv_bfloat16 lb[4];
#pragma unroll
    for (int j = 0; j < 4; j++) {
        hb[j] = __float2bfloat16(f[j]);
        lb[j] = __float2bfloat16(f[j] - __bfloat162float(hb[j]));
    }
    *(uint2*)(hi + i) = *(uint2*)hb;
    *(uint2*)(lo + i) = *(uint2*)lb;
}

// ---------------------------------------------------------------------------
// W [K,N] fp32 row-major -> W^T hi/lo bf16 [N,K]
// ---------------------------------------------------------------------------
__global__ __launch_bounds__(256) void cvt_w_t(
    const float* __restrict__ W, __nv_bfloat16* __restrict__ Thi,
    __nv_bfloat16* __restrict__ Tlo, int K, int N)
{
    __shared__ float tile[32][33];
    const int n0 = blockIdx.x * 32, k0 = blockIdx.y * 32;
    const int tx = threadIdx.x & 31, ty = threadIdx.x >> 5;   // 32 x 8
#pragma unroll
    for (int r = 0; r < 4; r++)
        tile[ty + 8 * r][tx] = W[(size_t)(k0 + ty + 8 * r) * N + n0 + tx];
    __syncthreads();
#pragma unroll
    for (int r = 0; r < 4; r++) {
        int n = n0 + ty + 8 * r;
        float v = tile[tx][ty + 8 * r];
        __nv_bfloat16 h = __float2bfloat16(v);
        __nv_bfloat16 l = __float2bfloat16(v - __bfloat162float(h));
        Thi[(size_t)n * K + k0 + tx] = h;
        Tlo[(size_t)n * K + k0 + tx] = l;
    }
}

// ---------------------------------------------------------------------------
// mma.sync bf16x3 GEMM: C[M,N] = A[M,K] @ B^T  (A [M,K], B [N,K], hi/lo bf16)
// CTA: 128x128 tile, BK=32, 256 threads (8 warps, 2Mx4N, warp tile 64x32),
// cp.async double-buffered. MODE 0: fp32 out; MODE 1: hi/lo bf16 out.
// ---------------------------------------------------------------------------
#define BK_G   32
#define LDT    40                       // 32 + 8 pad (bf16 elems) -> 80B rows
#define MAT_B  (128 * LDT * 2)          // 10240 B per matrix (128 rows)
#define BUF_B  (4 * MAT_B)              // Ahi Alo Bhi Blo = 40960 B
#define SMEM_GEMM (2 * BUF_B)           // 81920 B

template<int MODE>
__global__ __launch_bounds__(256, 1)
void gemm_mma_bf16x3(const __nv_bfloat16* __restrict__ Ahi,
                     const __nv_bfloat16* __restrict__ Alo,
                     const __nv_bfloat16* __restrict__ Bhi,
                     const __nv_bfloat16* __restrict__ Blo,
                     float* __restrict__ Cf,
                     __nv_bfloat16* __restrict__ Chi,
                     __nv_bfloat16* __restrict__ Clo,
                     int N, int K)
{
    extern __shared__ __align__(128) char smem[];
    const int t    = threadIdx.x;
    const int lane = t & 31;
    const int wid  = t >> 5;
    const int bn   = blockIdx.x * 128;
    const int bm   = blockIdx.y * 128;
    const int wm   = (wid & 1) * 64;
    const int wn   = (wid >> 1) * 32;

    float acc[4][4][4];
#pragma unroll
    for (int i = 0; i < 4; i++)
#pragma unroll
        for (int j = 0; j < 4; j++)
#pragma unroll
            for (int r = 0; r < 4; r++) acc[i][j][r] = 0.f;

    const int nk = K / BK_G;

    auto load_tile = [&](int c, int buf) {
        char* bp = smem + buf * BUF_B;
        const int kc = c * BK_G;
#pragma unroll
        for (int i = 0; i < 2; i++) {
            int idx = t + 256 * i;
            int row = idx >> 2;
            int c16 = idx & 3;
            uint32_t so = (uint32_t)(row * LDT + c16 * 8) * 2;
            size_t ga = (size_t)(bm + row) * K + kc + c16 * 8;
            size_t gb = (size_t)(bn + row) * K + kc + c16 * 8;
            cp16(bp + so,             Ahi + ga);
            cp16(bp + MAT_B + so,     Alo + ga);
            cp16(bp + 2 * MAT_B + so, Bhi + gb);
            cp16(bp + 3 * MAT_B + so, Blo + gb);
        }
    };

    load_tile(0, 0);
    asm volatile("cp.async.commit_group;" ::: "memory");

    for (int c = 0; c < nk; c++) {
        if (c + 1 < nk) {
            load_tile(c + 1, (c + 1) & 1);
            asm volatile("cp.async.commit_group;" ::: "memory");
            asm volatile("cp.async.wait_group 1;" ::: "memory");
        } else {
            asm volatile("cp.async.wait_group 0;" ::: "memory");
        }
        __syncthreads();

        const char* bp = smem + (c & 1) * BUF_B;
        const __nv_bfloat16* sAhi = (const __nv_bfloat16*)(bp);
        const __nv_bfloat16* sAlo = (const __nv_bfloat16*)(bp + MAT_B);
        const __nv_bfloat16* sBhi = (const __nv_bfloat16*)(bp + 2 * MAT_B);
        const __nv_bfloat16* sBlo = (const __nv_bfloat16*)(bp + 3 * MAT_B);

#pragma unroll
        for (int ks = 0; ks < BK_G; ks += 16) {
            uint32_t ah[4][4], al[4][4], bh[2][4], bl[2][4];
            const int arow = lane & 15;
            const int acol = ks + (lane >> 4) * 8;
#pragma unroll
            for (int mf = 0; mf < 4; mf++) {
                uint32_t off = (uint32_t)((wm + mf * 16 + arow) * LDT + acol);
                ldx4(ah[mf], smem_u32(sAhi + off));
                ldx4(al[mf], smem_u32(sAlo + off));
            }
            const int g    = lane >> 3;
            const int brow = ((g >> 1) << 3) + (lane & 7);
            const int bcol = ks + (g & 1) * 8;
#pragma unroll
            for (int nf2 = 0; nf2 < 2; nf2++) {
                uint32_t off = (uint32_t)((wn + nf2 * 16 + brow) * LDT + bcol);
                ldx4(bh[nf2], smem_u32(sBhi + off));
                ldx4(bl[nf2], smem_u32(sBlo + off));
            }
#pragma unroll
            for (int mf = 0; mf < 4; mf++)
#pragma unroll
                for (int nf2 = 0; nf2 < 2; nf2++)
#pragma unroll
                    for (int j = 0; j < 2; j++) {
                        float* d = acc[mf][nf2 * 2 + j];
                        mma_bf16(d, ah[mf], &bh[nf2][j * 2]);
                        mma_bf16(d, ah[mf], &bl[nf2][j * 2]);
                        mma_bf16(d, al[mf], &bh[nf2][j * 2]);
                    }
        }
        __syncthreads();
    }

#pragma unroll
    for (int mf = 0; mf < 4; mf++)
#pragma unroll
        for (int nf = 0; nf < 4; nf++) {
            int row = bm + wm + mf * 16 + (lane >> 2);
            int col = bn + wn + nf * 8 + (lane & 3) * 2;
            if (MODE == 0) {
                *(float2*)&Cf[(size_t)row * N + col] =
                    make_float2(acc[mf][nf][0], acc[mf][nf][1]);
                *(float2*)&Cf[(size_t)(row + 8) * N + col] =
                    make_float2(acc[mf][nf][2], acc[mf][nf][3]);
            } else {
                uint32_t h, l;
                pack_hilo(acc[mf][nf][0], acc[mf][nf][1], h, l);
                *(uint32_t*)&Chi[(size_t)row * N + col] = h;
                *(uint32_t*)&Clo[(size_t)row * N + col] = l;
                pack_hilo(acc[mf][nf][2], acc[mf][nf][3], h, l);
                *(uint32_t*)&Chi[(size_t)(row + 8) * N + col] = h;
                *(uint32_t*)&Clo[(size_t)(row + 8) * N + col] = l;
            }
        }
}

// ---------------------------------------------------------------------------
// Tensor-core flash attention (bf16x3 hi/lo, fp32 accum).
// CTA: 128 threads (4 warps), BLOCK_M=64 q, BLOCK_N=64 k. Warp owns 16 q rows.
// Inputs: QKV hi/lo bf16 [token, 3C]. Output: hi/lo bf16 [token, C] (proj input).
// smem rows padded to 72 bf16 (144B) -> conflict-free ldmatrix (+4 banks/row).
// ---------------------------------------------------------------------------
#define LDA_A 72
#define TILE_E (64 * LDA_A)                 // elems per smem matrix
#define ATTN_SMEM (6 * TILE_E * 2)          // Qh Ql Kh Kl Vh Vl = 55296 B

__global__ __launch_bounds__(128) void attn_mma(
    const __nv_bfloat16* __restrict__ Shi, const __nv_bfloat16* __restrict__ Slo,
    __nv_bfloat16* __restrict__ Yhi, __nv_bfloat16* __restrict__ Ylo)
{
    extern __shared__ __align__(16) char smraw[];
    __nv_bfloat16* Qh = (__nv_bfloat16*)smraw;
    __nv_bfloat16* Ql = Qh + TILE_E;
    __nv_bfloat16* Kh = Ql + TILE_E;
    __nv_bfloat16* Kl = Kh + TILE_E;
    __nv_bfloat16* Vh = Kl + TILE_E;
    __nv_bfloat16* Vl = Vh + TILE_E;

    const int it = blockIdx.x;          // q-tile (0..31)
    const int h  = blockIdx.y;
    const int b  = blockIdx.z;
    const int t  = threadIdx.x;
    const int lane = t & 31;
    const int wid  = t >> 5;
    const int wq   = wid * 16;          // warp's q-row offset in tile

    const int q0   = it * 64;
    const size_t tok0 = (size_t)b * L_;
    const int qcol = h * D_;
    const int kcol = C_ + h * D_;
    const int vcol = 2 * C_ + h * D_;

    // ---- stage Q tile (hi/lo), 64 rows x 128B each ----
#pragma unroll
    for (int i = 0; i < 4; i++) {
        int idx = t + 128 * i;
        int row = idx >> 3;
        int ch  = (idx & 7) * 8;
        size_t g = (tok0 + q0 + row) * (3 * C_) + qcol + ch;
        cp16(Qh + row * LDA_A + ch, Shi + g);
        cp16(Ql + row * LDA_A + ch, Slo + g);
    }
    asm volatile("cp.async.commit_group;" ::: "memory");
    asm volatile("cp.async.wait_group 0;" ::: "memory");
    __syncthreads();

    // ---- Q fragments (A-frags, m16k16 x 4 kgroups, hi+lo) ----
    uint32_t qh[4][4], ql[4][4];
    {
        const int arow = lane & 15;
        const int acol = (lane >> 4) * 8;
#pragma unroll
        for (int kg = 0; kg < 4; kg++) {
            uint32_t off = (uint32_t)((wq + arow) * LDA_A + kg * 16 + acol);
            ldx4(qh[kg], smem_u32(Qh + off));
            ldx4(ql[kg], smem_u32(Ql + off));
        }
    }

    const int r0 = lane >> 2;           // row pair within m16
    float m[2] = {-1e30f, -1e30f};
    float lsum[2] = {0.f, 0.f};
    float O[8][4];
#pragma unroll
    for (int f = 0; f < 8; f++)
#pragma unroll
        for (int e = 0; e < 4; e++) O[f][e] = 0.f;

    for (int jb = 0; jb <= it; jb++) {
        const int k0 = jb * 64;
        __syncthreads();   // all warps done with previous K/V tiles

        // ---- stage K/V tiles (hi/lo) ----
#pragma unroll
        for (int i = 0; i < 4; i++) {
            int idx = t + 128 * i;
            int row = idx >> 3;
            int ch  = (idx & 7) * 8;
            size_t gk = (tok0 + k0 + row) * (3 * C_) + kcol + ch;
            size_t gv = (tok0 + k0 + row) * (3 * C_) + vcol + ch;
            uint32_t so = row * LDA_A + ch;
            cp16(Kh + so, Shi + gk);
            cp16(Kl + so, Slo + gk);
            cp16(Vh + so, Shi + gv);
            cp16(Vl + so, Slo + gv);
        }
        asm volatile("cp.async.commit_group;" ::: "memory");
        asm volatile("cp.async.wait_group 0;" ::: "memory");
        __syncthreads();

        // ---- S = Q K^T (scores frags: 8 x n8) ----
        float s[8][4];
#pragma unroll
        for (int f = 0; f < 8; f++)
#pragma unroll
            for (int e = 0; e < 4; e++) s[f][e] = 0.f;

        {
            const int g    = lane >> 3;
            const int brow = ((g >> 1) << 3) + (lane & 7);
            const int bcol = (g & 1) * 8;
#pragma unroll
            for (int kg = 0; kg < 4; kg++) {
#pragma unroll
                for (int nf2 = 0; nf2 < 4; nf2++) {
                    uint32_t kh[4], kl[4];
                    uint32_t off = (uint32_t)((nf2 * 16 + brow) * LDA_A + kg * 16 + bcol);
                    ldx4(kh, smem_u32(Kh + off));
                    ldx4(kl, smem_u32(Kl + off));
#pragma unroll
                    for (int j = 0; j < 2; j++) {
                        float* d = s[nf2 * 2 + j];
                        mma_bf16(d, qh[kg], &kh[j * 2]);
                        mma_bf16(d, qh[kg], &kl[j * 2]);
                        mma_bf16(d, ql[kg], &kh[j * 2]);
                    }
                }
            }
        }

        // ---- scale + causal mask ----
        const bool diag = (jb == it);
#pragma unroll
        for (int f = 0; f < 8; f++) {
#pragma unroll
            for (int e = 0; e < 4; e++) {
                int qi = q0 + wq + r0 + (e >> 1) * 8;
                int ki = k0 + f * 8 + (lane & 3) * 2 + (e & 1);
                float v = s[f][e] * 0.125f;
                s[f][e] = (diag && ki > qi) ? -1e30f : v;
            }
        }

        // ---- online softmax (rows r0, r0+8) ----
#pragma unroll
        for (int r = 0; r < 2; r++) {
            float vmax = -1e30f;
#pragma unroll
            for (int f = 0; f < 8; f++)
                vmax = fmaxf(vmax, fmaxf(s[f][2 * r], s[f][2 * r + 1]));
            vmax = fmaxf(vmax, __shfl_xor_sync(0xffffffffu, vmax, 1));
            vmax = fmaxf(vmax, __shfl_xor_sync(0xffffffffu, vmax, 2));
            float nm = fmaxf(m[r], vmax);
            float alpha = __expf(m[r] - nm);
            m[r] = nm;
            float rs = 0.f;
#pragma unroll
            for (int f = 0; f < 8; f++) {
                float p0 = __expf(s[f][2 * r] - nm);
                float p1 = __expf(s[f][2 * r + 1] - nm);
                s[f][2 * r] = p0; s[f][2 * r + 1] = p1;
                rs += p0 + p1;
            }
            rs += __shfl_xor_sync(0xffffffffu, rs, 1);
            rs += __shfl_xor_sync(0xffffffffu, rs, 2);
            lsum[r] = lsum[r] * alpha + rs;
#pragma unroll
            for (int f = 0; f < 8; f++) {
                O[f][2 * r] *= alpha;
                O[f][2 * r + 1] *= alpha;
            }
        }

        // ---- O += P V (P packed from score frags; V via ldmatrix.trans) ----
        {
            const int g = lane >> 3;
            const int vrow = (g & 1) * 8 + (lane & 7);
            const int vcolb = (g >> 1) * 8;
#pragma unroll
            for (int kg = 0; kg < 4; kg++) {
                uint32_t pa_h[4], pa_l[4];
                pack_hilo(s[2 * kg][0],     s[2 * kg][1],     pa_h[0], pa_l[0]);
                pack_hilo(s[2 * kg][2],     s[2 * kg][3],     pa_h[1], pa_l[1]);
                pack_hilo(s[2 * kg + 1][0], s[2 * kg + 1][1], pa_h[2], pa_l[2]);
                pack_hilo(s[2 * kg + 1][2], s[2 * kg + 1][3], pa_h[3], pa_l[3]);
#pragma unroll
                for (int nf2 = 0; nf2 < 4; nf2++) {
                    uint32_t vh[4], vl[4];
                    uint32_t off = (uint32_t)((kg * 16 + vrow) * LDA_A + nf2 * 16 + vcolb);
                    ldx4t(vh, smem_u32(Vh + off));
                    ldx4t(vl, smem_u32(Vl + off));
#pragma unroll
                    for (int j = 0; j < 2; j++) {
                        float* d = O[nf2 * 2 + j];
                        mma_bf16(d, pa_h, &vh[j * 2]);
                        mma_bf16(d, pa_h, &vl[j * 2]);
                        mma_bf16(d, pa_l, &vh[j * 2]);
                    }
                }
            }
        }
    }

    // ---- normalize + write hi/lo bf16 output [token, C] ----
    const float inv0 = 1.0f / lsum[0];
    const float inv1 = 1.0f / lsum[1];
#pragma unroll
    for (int f = 0; f < 8; f++) {
        int col = h * D_ + f * 8 + (lane & 3) * 2;
        size_t row0 = (tok0 + q0 + wq + r0) * C_ + col;
        size_t row1 = (tok0 + q0 + wq + r0 + 8) * C_ + col;
        uint32_t hh, ll;
        pack_hilo(O[f][0] * inv0, O[f][1] * inv0, hh, ll);
        *(uint32_t*)&Yhi[row0] = hh;
        *(uint32_t*)&Ylo[row0] = ll;
        pack_hilo(O[f][2] * inv1, O[f][3] * inv1, hh, ll);
        *(uint32_t*)&Yhi[row1] = hh;
        *(uint32_t*)&Ylo[row1] = ll;
    }
}

// ---------------------------------------------------------------------------

extern "C" void kernel_launch(void* const* d_in, const int* in_sizes, int n_in,
                              void* d_out, int out_size)
{
    const float* x      = (const float*)d_in[0];   // [4,2048,1024]
    const float* w_attn = (const float*)d_in[1];   // [1024,3072]
    const float* w_proj = (const float*)d_in[2];   // [1024,1024]
    float* out = (float*)d_out;                    // [4,2048,1024]

    __nv_bfloat16 *ahi, *alo, *bhi, *blo, *shi, *slo;
    cudaGetSymbolAddress((void**)&ahi, g_Ahi);
    cudaGetSymbolAddress((void**)&alo, g_Alo);
    cudaGetSymbolAddress((void**)&bhi, g_Bhi);
    cudaGetSymbolAddress((void**)&blo, g_Blo);
    cudaGetSymbolAddress((void**)&shi, g_Shi);
    cudaGetSymbolAddress((void**)&slo, g_Slo);

    cudaFuncSetAttribute(gemm_mma_bf16x3<0>,
                         cudaFuncAttributeMaxDynamicSharedMemorySize, SMEM_GEMM);
    cudaFuncSetAttribute(gemm_mma_bf16x3<1>,
                         cudaFuncAttributeMaxDynamicSharedMemorySize, SMEM_GEMM);
    cudaFuncSetAttribute(attn_mma,
                         cudaFuncAttributeMaxDynamicSharedMemorySize, ATTN_SMEM);

    const int nA = MTOK * C_;

    // 1) split x -> bf16 hi/lo ; transpose+split w_attn -> [3C, C]
    cvt_hilo<<<nA / 4 / 256, 256>>>(x, ahi, alo, nA);
    cvt_w_t<<<dim3(3 * C_ / 32, C_ / 32), 256>>>(w_attn, bhi, blo, C_, 3 * C_);

    // 2) QKV GEMM -> hi/lo bf16 QKV directly
    gemm_mma_bf16x3<1><<<dim3(3 * C_ / 128, MTOK / 128), 256, SMEM_GEMM>>>(
        ahi, alo, bhi, blo, nullptr, shi, slo, 3 * C_, C_);

    // 3) tensor-core causal flash attention -> hi/lo bf16 into proj input bufs
    attn_mma<<<dim3(L_ / 64, H_, B_), 128, ATTN_SMEM>>>(shi, slo, ahi, alo);

    // 4) transpose+split w_proj
    cvt_w_t<<<dim3(C_ / 32, C_ / 32), 256>>>(w_proj, bhi, blo, C_, C_);

    // 5) proj GEMM -> fp32 out
    gemm_mma_bf16x3<0><<<dim3(C_ / 128, MTOK / 128), 256, SMEM_GEMM>>>(
        ahi, alo, bhi, blo, out, nullptr, nullptr, C_, C_);
}